// round 13
// baseline (speedup 1.0000x reference)
#include <cuda_runtime.h>
#include <cuda_fp16.h>
#include <math.h>
#include <stdint.h>

// ---------------------------------------------------------------------------
// Problem constants
// ---------------------------------------------------------------------------
#define Bn    4096
#define DH    784
#define DHP   832                 // padded K (13 * 64)
#define DE    16
#define NSR   5
#define NTOT  (Bn * (1 + NSR))
#define NTILE 32
#define NBLK  (NTILE * (NTILE + 1) / 2)   // 528
#define NCH   13                  // K chunks of 64 halves (last = 1 ks only)
#define NPRB  2048                // prep row-blocks (2 rows each)
#define NCE2  55                  // CE blocks appended to prep (448 thr each)
#define NCOB  16                  // corr blocks in work_k
#define NPART (NCE2 + NCOB)       // 71

#define ALPHA 0.9296875
#define BETA  0.0703125

__device__ __constant__ const float A_C  = 1.576943f;
__device__ __constant__ const float PW   = 1.7901216f;
__device__ __constant__ const float EPSc = 1e-4f;

// smem layout (bytes) — identical to the R4/R12 pair_k
#define SM_A    0            // [2][128][64] halves = 32768
#define SM_B    32768        // 32768
#define SM_EA   65536        // [128][16] halves = 4096
#define SM_EB   69632        // 4096
#define SM_ROW  73728        // [4][128][5] f32 = 10240
#define SM_COL  83968        // [2][128][5] f32 = 5120
#define SM_NHI  89088        // 512 each
#define SM_NHJ  89600
#define SM_NLI  90112
#define SM_NLJ  90624
#define SM_TOT  91136

// ---------------------------------------------------------------------------
// Device scratch
// ---------------------------------------------------------------------------
__device__ __half  g_Xh[(size_t)Bn * DHP];  // fp16 X, zero-padded
__device__ __half  g_Eh[(size_t)Bn * DE];   // fp16 e_to
__device__ double  g_Sh[Bn], g_Sl[Bn], g_Shh[Bn], g_Sll[Bn], g_Shl[Bn];
__device__ float   g_sqh[Bn];
__device__ float   g_sql[Bn];
__device__ double  g_part[NPART];
__device__ unsigned g_done;

// ---------------------------------------------------------------------------
// Helpers
// ---------------------------------------------------------------------------
__device__ __forceinline__ unsigned h2u(__half2 h) {
    union { __half2 h; unsigned u; } c; c.h = h; return c.u;
}
__device__ __forceinline__ uint32_t s2u(const void* p) {
    uint32_t a;
    asm("{ .reg .u64 t; cvta.to.shared.u64 t, %1; cvt.u32.u64 %0, t; }"
        : "=r"(a) : "l"(p));
    return a;
}
__device__ __forceinline__ float sqrt_fast(float x) {
    float y; asm("sqrt.approx.f32 %0, %1;" : "=f"(y) : "f"(x)); return y;
}
__device__ __forceinline__ float lg2_fast(float x) {
    float y; asm("lg2.approx.f32 %0, %1;" : "=f"(y) : "f"(x)); return y;
}
__device__ __forceinline__ float ex2_fast(float x) {
    float y; asm("ex2.approx.f32 %0, %1;" : "=f"(y) : "f"(x)); return y;
}
__device__ __forceinline__ void cpa16(uint32_t dst, const void* src) {
    asm volatile("cp.async.cg.shared.global [%0], [%1], 16;"
                 :: "r"(dst), "l"(src) : "memory");
}
__device__ __forceinline__ void ldsm4(uint32_t* r, uint32_t addr) {
    asm volatile("ldmatrix.sync.aligned.m8n8.x4.shared.b16 {%0,%1,%2,%3}, [%4];"
                 : "=r"(r[0]), "=r"(r[1]), "=r"(r[2]), "=r"(r[3]) : "r"(addr));
}
__device__ __forceinline__ void mma16816(float* d, const uint32_t* a, const uint32_t* b) {
    asm volatile(
        "mma.sync.aligned.m16n8k16.row.col.f32.f16.f16.f32 "
        "{%0,%1,%2,%3}, {%4,%5,%6,%7}, {%8,%9}, {%0,%1,%2,%3};"
        : "+f"(d[0]), "+f"(d[1]), "+f"(d[2]), "+f"(d[3])
        : "r"(a[0]), "r"(a[1]), "r"(a[2]), "r"(a[3]), "r"(b[0]), "r"(b[1]));
}

// ---------------------------------------------------------------------------
// Kernel 0: prep — 2 rows/block fp16 conversion + norms (blocks < NPRB),
//           CE partials (blocks >= NPRB). 448 threads.
// ---------------------------------------------------------------------------
__global__ void __launch_bounds__(448) prep_k(const float* __restrict__ X,
                                              const float* __restrict__ E,
                                              const int* __restrict__ perm) {
    int b = blockIdx.x;
    int t = threadIdx.x;
    int lane = t & 31, w = t >> 5;

    if (b < NPRB) {
        int half = (t >= 224);
        int row = b * 2 + half;
        int tl = t - half * 224;
        float s = 0.f, se = 0.f;

        if (tl < 196) {
            float4 v = *(const float4*)(X + (size_t)row * DH + tl * 4);
            __half2 h01 = __floats2half2_rn(v.x, v.y);
            __half2 h23 = __floats2half2_rn(v.z, v.w);
            float2 f0 = __half22float2(h01);
            float2 f1 = __half22float2(h23);
            s = fmaf(f0.x, f0.x, fmaf(f0.y, f0.y, fmaf(f1.x, f1.x, f1.y * f1.y)));
            *(uint2*)(g_Xh + (size_t)row * DHP + tl * 4) = make_uint2(h2u(h01), h2u(h23));
        } else if (tl < 208) {
            *(uint2*)(g_Xh + (size_t)row * DHP + DH + (tl - 196) * 4) = make_uint2(0u, 0u);
        } else {
            int k = tl - 208;
            __half h = __float2half(E[(size_t)row * 32 + k]);
            g_Eh[(size_t)row * DE + k] = h;
            float v = __half2float(h);
            se = v * v;
        }
        #pragma unroll
        for (int o = 16; o; o >>= 1) {
            s  += __shfl_xor_sync(0xffffffffu, s, o);
            se += __shfl_xor_sync(0xffffffffu, se, o);
        }
        __shared__ float ws[14], wse[2];
        if (lane == 0) {
            ws[w] = s;
            if (w == 6)  wse[0] = se;
            if (w == 13) wse[1] = se;
        }
        __syncthreads();
        if (t == 0 || t == 224) {
            int base = half * 7;
            float tot = 0.f;
            #pragma unroll
            for (int q = 0; q < 7; q++) tot += ws[base + q];
            g_sqh[row] = tot;
            g_sql[row] = wse[half];
            g_Sh[row] = 0.0; g_Sl[row] = 0.0; g_Shh[row] = 0.0;
            g_Sll[row] = 0.0; g_Shl[row] = 0.0;
            if (b == 0 && t == 0) g_done = 0u;
        }
    } else {
        // CE blocks: 55 x 448 threads covers NTOT=24576
        int ceb = b - NPRB;
        int idx = ceb * 448 + t;
        float val = 0.f;
        if (idx < NTOT) {
            float sq = 0.f;
            if (idx < Bn) {
                const float* p = E + (size_t)idx * 32;
                #pragma unroll
                for (int k = 0; k < DE; k++) { float d = p[k] - p[DE + k]; sq = fmaf(d, d, sq); }
                float pw = (sq > 0.f) ? ex2_fast(0.5f * PW * lg2_fast(sq)) : 0.f;
                float pd = 1.f / (1.f + A_C * pw);
                val = -0.69314718056f * lg2_fast(fmaxf(pd, EPSc));
            } else {
                int j = idx - Bn;
                const float* pt = E + (size_t)(j / NSR) * 32;
                const float* pf = E + (size_t)(perm[j] / NSR) * 32 + DE;
                #pragma unroll
                for (int k = 0; k < DE; k++) { float d = pt[k] - pf[k]; sq = fmaf(d, d, sq); }
                float pw = (sq > 0.f) ? ex2_fast(0.5f * PW * lg2_fast(sq)) : 0.f;
                float pd = 1.f / (1.f + A_C * pw);
                val = -0.69314718056f * lg2_fast(fmaxf(1.f - pd, EPSc));
            }
        }
        #pragma unroll
        for (int o = 16; o; o >>= 1) val += __shfl_xor_sync(0xffffffffu, val, o);
        __shared__ float cw[14];
        if (lane == 0) cw[w] = val;
        __syncthreads();
        if (t == 0) {
            float s2 = 0.f;
            #pragma unroll
            for (int q = 0; q < 14; q++) s2 += cw[q];
            g_part[ceb] = (double)s2;
        }
    }
}

// ---------------------------------------------------------------------------
// Kernel 1: HMMA pairwise-moment tiles — R12 body + peeled last chunk
// ---------------------------------------------------------------------------
__global__ void __launch_bounds__(256, 2) pair_k() {
    extern __shared__ __align__(16) char smem[];
    const uint32_t sb = s2u(smem);
    const int tid = threadIdx.x;
    const int lane = tid & 31, wid = tid >> 5;
    const int wr = wid >> 2, wc = wid & 3;

    // triangular tile decode
    int idx = blockIdx.x, bi = 0;
    while ((bi + 1) * (65 - (bi + 1)) / 2 <= idx) bi++;
    int bj = bi + (idx - bi * (65 - bi) / 2);
    const bool offdiag = (bi != bj);
    const int i0 = bi * 128, j0 = bj * 128;

    float* nhI = (float*)(smem + SM_NHI);
    float* nhJ = (float*)(smem + SM_NHJ);
    float* nlI = (float*)(smem + SM_NLI);
    float* nlJ = (float*)(smem + SM_NLJ);
    if (tid < 128) {
        nhI[tid] = g_sqh[i0 + tid];
        nlI[tid] = g_sql[i0 + tid];
    } else {
        int r = tid - 128;
        nhJ[r] = g_sqh[j0 + r];
        nlJ[r] = g_sql[j0 + r];
    }

    const __half* XA = g_Xh + (size_t)i0 * DHP;
    const __half* XB = g_Xh + (size_t)j0 * DHP;

    // E tiles (1 cp.async per thread per side)
    {
        int row = tid >> 1, u = tid & 1;
        cpa16(sb + SM_EA + row * 32 + u * 16, g_Eh + (size_t)(i0 + row) * DE + u * 8);
        cpa16(sb + SM_EB + row * 32 + u * 16, g_Eh + (size_t)(j0 + row) * DE + u * 8);
    }
    // chunk 0
    #pragma unroll
    for (int p = 0; p < 4; p++) {
        int id = tid + p * 256;
        int row = id >> 3, u = id & 7;
        uint32_t sw = (uint32_t)((u ^ (row & 7)) << 4);
        cpa16(sb + SM_A + row * 128 + sw, XA + (size_t)row * DHP + u * 8);
        cpa16(sb + SM_B + row * 128 + sw, XB + (size_t)row * DHP + u * 8);
    }
    asm volatile("cp.async.commit_group;" ::: "memory");
    asm volatile("cp.async.wait_group 0;" ::: "memory");
    __syncthreads();

    // per-thread fragment address components
    const int rbaseA = wr * 64 + (lane & 15);
    const int duA    = lane >> 4;
    const int rmA    = rbaseA & 7;
    const int nbase  = wc * 32 + (lane & 7) + ((lane >> 4) << 3);
    const int duB    = (lane >> 3) & 1;
    const int rmB    = lane & 7;

    float acc[4][4][4];
    #pragma unroll
    for (int a = 0; a < 4; a++)
        #pragma unroll
        for (int b = 0; b < 4; b++)
            #pragma unroll
            for (int c = 0; c < 4; c++) acc[a][b][c] = 0.f;

    // ---------------- low-D (16) gram: single k-step ----------------
    {
        uint32_t ea[4][4], eb[2][4];
        #pragma unroll
        for (int mi = 0; mi < 4; mi++) {
            int rE = rbaseA + mi * 16;
            ldsm4(ea[mi], sb + SM_EA + rE * 32 + (duA << 4));
        }
        #pragma unroll
        for (int nt = 0; nt < 2; nt++) {
            int nE = nbase + nt * 16;
            ldsm4(eb[nt], sb + SM_EB + nE * 32 + (duB << 4));
        }
        #pragma unroll
        for (int mi = 0; mi < 4; mi++)
            #pragma unroll
            for (int ni = 0; ni < 4; ni++)
                mma16816(acc[mi][ni], ea[mi], &eb[ni >> 1][(ni & 1) * 2]);
    }
    // convert to l distances (half2), reset acc
    __half2 lhp[4][4][2];
    #pragma unroll
    for (int mi = 0; mi < 4; mi++) {
        int r0 = wr * 64 + mi * 16 + (lane >> 2), r1 = r0 + 8;
        float nl0 = nlI[r0], nl1 = nlI[r1];
        #pragma unroll
        for (int ni = 0; ni < 4; ni++) {
            int c0 = wc * 32 + ni * 8 + ((lane & 3) << 1), c1 = c0 + 1;
            float ol0 = nlJ[c0], ol1 = nlJ[c1];
            float l00 = sqrt_fast(fmaxf(fmaf(-2.f, acc[mi][ni][0], nl0 + ol0), 0.f));
            float l01 = sqrt_fast(fmaxf(fmaf(-2.f, acc[mi][ni][1], nl0 + ol1), 0.f));
            float l10 = sqrt_fast(fmaxf(fmaf(-2.f, acc[mi][ni][2], nl1 + ol0), 0.f));
            float l11 = sqrt_fast(fmaxf(fmaf(-2.f, acc[mi][ni][3], nl1 + ol1), 0.f));
            lhp[mi][ni][0] = __floats2half2_rn(l00, l01);
            lhp[mi][ni][1] = __floats2half2_rn(l10, l11);
            acc[mi][ni][0] = 0.f; acc[mi][ni][1] = 0.f;
            acc[mi][ni][2] = 0.f; acc[mi][ni][3] = 0.f;
        }
    }

    // ---------------- high-D mainloop: chunks 0..11 (full 4 ks each) -------
    for (int c = 0; c < NCH - 1; c++) {
        {
            uint32_t dA = sb + SM_A + (((c + 1) & 1) << 14);
            uint32_t dB = sb + SM_B + (((c + 1) & 1) << 14);
            const __half* pA = XA + (c + 1) * 64;
            const __half* pB = XB + (c + 1) * 64;
            #pragma unroll
            for (int p = 0; p < 4; p++) {
                int id = tid + p * 256;
                int row = id >> 3, u = id & 7;
                uint32_t sw = (uint32_t)((u ^ (row & 7)) << 4);
                cpa16(dA + row * 128 + sw, pA + (size_t)row * DHP + u * 8);
                cpa16(dB + row * 128 + sw, pB + (size_t)row * DHP + u * 8);
            }
            asm volatile("cp.async.commit_group;" ::: "memory");
            asm volatile("cp.async.wait_group 1;" ::: "memory");
        }
        __syncthreads();

        uint32_t bA = sb + SM_A + ((c & 1) << 14);
        uint32_t bB = sb + SM_B + ((c & 1) << 14);
        #pragma unroll
        for (int ks = 0; ks < 4; ks++) {
            uint32_t afr[4][4], bfr[2][4];
            #pragma unroll
            for (int mi = 0; mi < 4; mi++) {
                int row = rbaseA + mi * 16;
                ldsm4(afr[mi], bA + row * 128 + (((2 * ks + duA) ^ rmA) << 4));
            }
            #pragma unroll
            for (int nt = 0; nt < 2; nt++) {
                int nb = nbase + nt * 16;
                ldsm4(bfr[nt], bB + nb * 128 + (((2 * ks + duB) ^ rmB) << 4));
            }
            #pragma unroll
            for (int mi = 0; mi < 4; mi++)
                #pragma unroll
                for (int ni = 0; ni < 4; ni++)
                    mma16816(acc[mi][ni], afr[mi], &bfr[ni >> 1][(ni & 1) * 2]);
        }
        __syncthreads();
    }
    // ---------------- peeled chunk 12: cols 768..831, only ks=0 is real ----
    {
        asm volatile("cp.async.wait_group 0;" ::: "memory");
        __syncthreads();
        uint32_t bA = sb + SM_A;        // chunk 12 landed in buffer 0 (12&1==0)
        uint32_t bB = sb + SM_B;
        uint32_t afr[4][4], bfr[2][4];
        #pragma unroll
        for (int mi = 0; mi < 4; mi++) {
            int row = rbaseA + mi * 16;
            ldsm4(afr[mi], bA + row * 128 + ((duA ^ rmA) << 4));
        }
        #pragma unroll
        for (int nt = 0; nt < 2; nt++) {
            int nb = nbase + nt * 16;
            ldsm4(bfr[nt], bB + nb * 128 + ((duB ^ rmB) << 4));
        }
        #pragma unroll
        for (int mi = 0; mi < 4; mi++)
            #pragma unroll
            for (int ni = 0; ni < 4; ni++)
                mma16816(acc[mi][ni], afr[mi], &bfr[ni >> 1][(ni & 1) * 2]);
        __syncthreads();
    }

    // ---------------- epilogue: distances + moments ----------------
    float* rowSm = (float*)(smem + SM_ROW);
    float* colSm = (float*)(smem + SM_COL);
    float cacc[4][2][5];
    #pragma unroll
    for (int ni = 0; ni < 4; ni++)
        #pragma unroll
        for (int q = 0; q < 2; q++)
            #pragma unroll
            for (int m = 0; m < 5; m++) cacc[ni][q][m] = 0.f;

    #pragma unroll
    for (int mi = 0; mi < 4; mi++) {
        int r0 = wr * 64 + mi * 16 + (lane >> 2), r1 = r0 + 8;
        float nh0 = nhI[r0], nh1 = nhI[r1];
        float rA[5] = {0.f, 0.f, 0.f, 0.f, 0.f};
        float rB[5] = {0.f, 0.f, 0.f, 0.f, 0.f};
        #pragma unroll
        for (int ni = 0; ni < 4; ni++) {
            int c0 = wc * 32 + ni * 8 + ((lane & 3) << 1), c1 = c0 + 1;
            float oh0 = nhJ[c0], oh1 = nhJ[c1];
            float h00 = sqrt_fast(fmaxf(fmaf(-2.f, acc[mi][ni][0], nh0 + oh0), 0.f));
            float h01 = sqrt_fast(fmaxf(fmaf(-2.f, acc[mi][ni][1], nh0 + oh1), 0.f));
            float h10 = sqrt_fast(fmaxf(fmaf(-2.f, acc[mi][ni][2], nh1 + oh0), 0.f));
            float h11 = sqrt_fast(fmaxf(fmaf(-2.f, acc[mi][ni][3], nh1 + oh1), 0.f));
            float2 lp0 = __half22float2(lhp[mi][ni][0]);
            float2 lp1 = __half22float2(lhp[mi][ni][1]);
            rA[0] += h00 + h01;
            rA[1] += lp0.x + lp0.y;
            rA[2] = fmaf(h00, h00, fmaf(h01, h01, rA[2]));
            rA[3] = fmaf(lp0.x, lp0.x, fmaf(lp0.y, lp0.y, rA[3]));
            rA[4] = fmaf(h00, lp0.x, fmaf(h01, lp0.y, rA[4]));
            rB[0] += h10 + h11;
            rB[1] += lp1.x + lp1.y;
            rB[2] = fmaf(h10, h10, fmaf(h11, h11, rB[2]));
            rB[3] = fmaf(lp1.x, lp1.x, fmaf(lp1.y, lp1.y, rB[3]));
            rB[4] = fmaf(h10, lp1.x, fmaf(h11, lp1.y, rB[4]));
            cacc[ni][0][0] += h00 + h10;
            cacc[ni][0][1] += lp0.x + lp1.x;
            cacc[ni][0][2] = fmaf(h00, h00, fmaf(h10, h10, cacc[ni][0][2]));
            cacc[ni][0][3] = fmaf(lp0.x, lp0.x, fmaf(lp1.x, lp1.x, cacc[ni][0][3]));
            cacc[ni][0][4] = fmaf(h00, lp0.x, fmaf(h10, lp1.x, cacc[ni][0][4]));
            cacc[ni][1][0] += h01 + h11;
            cacc[ni][1][1] += lp0.y + lp1.y;
            cacc[ni][1][2] = fmaf(h01, h01, fmaf(h11, h11, cacc[ni][1][2]));
            cacc[ni][1][3] = fmaf(lp0.y, lp0.y, fmaf(lp1.y, lp1.y, cacc[ni][1][3]));
            cacc[ni][1][4] = fmaf(h01, lp0.y, fmaf(h11, lp1.y, cacc[ni][1][4]));
        }
        #pragma unroll
        for (int m = 0; m < 5; m++) {
            rA[m] += __shfl_xor_sync(0xffffffffu, rA[m], 1);
            rA[m] += __shfl_xor_sync(0xffffffffu, rA[m], 2);
            rB[m] += __shfl_xor_sync(0xffffffffu, rB[m], 1);
            rB[m] += __shfl_xor_sync(0xffffffffu, rB[m], 2);
        }
        if ((lane & 3) == 0) {
            #pragma unroll
            for (int m = 0; m < 5; m++) {
                rowSm[(wc * 128 + r0) * 5 + m] = rA[m];
                rowSm[(wc * 128 + r1) * 5 + m] = rB[m];
            }
        }
    }
    #pragma unroll
    for (int ni = 0; ni < 4; ni++)
        #pragma unroll
        for (int q = 0; q < 2; q++)
            #pragma unroll
            for (int m = 0; m < 5; m++) {
                float v = cacc[ni][q][m];
                v += __shfl_xor_sync(0xffffffffu, v, 4);
                v += __shfl_xor_sync(0xffffffffu, v, 8);
                v += __shfl_xor_sync(0xffffffffu, v, 16);
                cacc[ni][q][m] = v;
            }
    if (lane < 4) {
        #pragma unroll
        for (int ni = 0; ni < 4; ni++) {
            int c0 = wc * 32 + ni * 8 + (lane << 1);
            #pragma unroll
            for (int m = 0; m < 5; m++) {
                colSm[(wr * 128 + c0) * 5 + m]     = cacc[ni][0][m];
                colSm[(wr * 128 + c0 + 1) * 5 + m] = cacc[ni][1][m];
            }
        }
    }
    __syncthreads();

    if (tid < 128) {
        int r = tid;
        float s0 = 0.f, s1 = 0.f, s2 = 0.f, s3 = 0.f, s4 = 0.f;
        #pragma unroll
        for (int w = 0; w < 4; w++) {
            const float* p = &rowSm[(w * 128 + r) * 5];
            s0 += p[0]; s1 += p[1]; s2 += p[2]; s3 += p[3]; s4 += p[4];
        }
        int gi = i0 + r;
        atomicAdd(&g_Sh[gi],  (double)s0);
        atomicAdd(&g_Sl[gi],  (double)s1);
        atomicAdd(&g_Shh[gi], (double)s2);
        atomicAdd(&g_Sll[gi], (double)s3);
        atomicAdd(&g_Shl[gi], (double)s4);
    } else if (offdiag) {
        int cjj = tid - 128;
        float s0 = 0.f, s1 = 0.f, s2 = 0.f, s3 = 0.f, s4 = 0.f;
        #pragma unroll
        for (int w = 0; w < 2; w++) {
            const float* p = &colSm[(w * 128 + cjj) * 5];
            s0 += p[0]; s1 += p[1]; s2 += p[2]; s3 += p[3]; s4 += p[4];
        }
        int gj = j0 + cjj;
        atomicAdd(&g_Sh[gj],  (double)s0);
        atomicAdd(&g_Sl[gj],  (double)s1);
        atomicAdd(&g_Shh[gj], (double)s2);
        atomicAdd(&g_Sll[gj], (double)s3);
        atomicAdd(&g_Shl[gj], (double)s4);
    }
}

// ---------------------------------------------------------------------------
// Kernel 2: corr partials (16 blocks); last block reduces CE+corr partials.
// ---------------------------------------------------------------------------
__global__ void __launch_bounds__(256) work_k(float* __restrict__ out) {
    int b = blockIdx.x;
    int t = threadIdx.x;
    int i = b * 256 + t;
    const double invB = 1.0 / (double)Bn;
    double Sh = g_Sh[i], Sl = g_Sl[i];
    float num = (float)(g_Shl[i] - Sh * Sl * invB);
    float vh  = (float)fmax(g_Shh[i] - Sh * Sh * invB, 0.0);
    float vl  = (float)fmax(g_Sll[i] - Sl * Sl * invB, 0.0);
    float val = num * rsqrtf(fmaxf(vh, 1e-30f)) * rsqrtf(fmaxf(vl, 1e-30f));

    #pragma unroll
    for (int o = 16; o; o >>= 1) val += __shfl_xor_sync(0xffffffffu, val, o);
    __shared__ float ws[8];
    __shared__ unsigned sticket;
    if ((t & 31) == 0) ws[t >> 5] = val;
    __syncthreads();
    if (t == 0) {
        float s2 = 0.f;
        #pragma unroll
        for (int w = 0; w < 8; w++) s2 += ws[w];
        g_part[NCE2 + b] = (double)s2;
        __threadfence();
        sticket = atomicAdd(&g_done, 1u);
    }
    __syncthreads();
    if (sticket == NCOB - 1) {
        double v = (t < NPART) ? ((volatile double*)g_part)[t] : 0.0;
        double ce = (t < NCE2) ? v : 0.0;
        double co = (t >= NCE2 && t < NPART) ? v : 0.0;
        #pragma unroll
        for (int o = 16; o; o >>= 1) {
            ce += __shfl_xor_sync(0xffffffffu, ce, o);
            co += __shfl_xor_sync(0xffffffffu, co, o);
        }
        __shared__ double rce[8], rco[8];
        if ((t & 31) == 0) { rce[t >> 5] = ce; rco[t >> 5] = co; }
        __syncthreads();
        if (t == 0) {
            double sce = 0.0, sco = 0.0;
            #pragma unroll
            for (int w = 0; w < 8; w++) { sce += rce[w]; sco += rco[w]; }
            out[0] = (float)(ALPHA * (sce / (double)NTOT) - BETA * (sco / (double)Bn));
        }
    }
}

// ---------------------------------------------------------------------------
extern "C" void kernel_launch(void* const* d_in, const int* in_sizes, int n_in,
                              void* d_out, int out_size) {
    (void)in_sizes; (void)n_in; (void)out_size;
    const float* E    = (const float*)d_in[0];
    const float* X    = (const float*)d_in[1];
    const int*   perm = (const int*)d_in[2];
    float* out = (float*)d_out;

    cudaFuncSetAttribute(pair_k, cudaFuncAttributeMaxDynamicSharedMemorySize, SM_TOT);

    prep_k<<<NPRB + NCE2, 448>>>(X, E, perm);
    pair_k<<<NBLK, 256, SM_TOT>>>();
    work_k<<<NCOB, 256>>>(out);
}

// round 14
// speedup vs baseline: 1.1843x; 1.1843x over previous
#include <cuda_runtime.h>
#include <cuda_fp16.h>
#include <math.h>
#include <stdint.h>

// ---------------------------------------------------------------------------
// Problem constants
// ---------------------------------------------------------------------------
#define Bn    4096
#define DH    784
#define DHP   832                 // padded K (13 * 64)
#define DE    16
#define NSR   5
#define NTOT  (Bn * (1 + NSR))
#define NTILE 32
#define NBLK  (NTILE * (NTILE + 1) / 2)   // 528
#define NCH   13                  // K chunks of 64 halves (last = 1 ks only)
#define NCEB  96                  // CE blocks in work_k
#define NCOB  16                  // corr blocks in work_k
#define NWRK  (NCEB + NCOB)

#define ALPHA 0.9296875
#define BETA  0.0703125

__device__ __constant__ const float A_C  = 1.576943f;
__device__ __constant__ const float PW   = 1.7901216f;
__device__ __constant__ const float EPSc = 1e-4f;

// smem layout (bytes) — identical to the R4/R12 pair_k
#define SM_A    0            // [2][128][64] halves = 32768
#define SM_B    32768        // 32768
#define SM_EA   65536        // [128][16] halves = 4096
#define SM_EB   69632        // 4096
#define SM_ROW  73728        // [4][128][5] f32 = 10240
#define SM_COL  83968        // [2][128][5] f32 = 5120
#define SM_NHI  89088        // 512 each
#define SM_NHJ  89600
#define SM_NLI  90112
#define SM_NLJ  90624
#define SM_TOT  91136

// ---------------------------------------------------------------------------
// Device scratch
// ---------------------------------------------------------------------------
__device__ __half  g_Xh[(size_t)Bn * DHP];  // fp16 X, zero-padded
__device__ __half  g_Eh[(size_t)Bn * DE];   // fp16 e_to
__device__ double  g_Sh[Bn], g_Sl[Bn], g_Shh[Bn], g_Sll[Bn], g_Shl[Bn];
__device__ float   g_sqh[Bn];
__device__ float   g_sql[Bn];
__device__ double  g_part[NWRK];
__device__ unsigned g_done;

// ---------------------------------------------------------------------------
// Helpers
// ---------------------------------------------------------------------------
__device__ __forceinline__ unsigned h2u(__half2 h) {
    union { __half2 h; unsigned u; } c; c.h = h; return c.u;
}
__device__ __forceinline__ uint32_t s2u(const void* p) {
    uint32_t a;
    asm("{ .reg .u64 t; cvta.to.shared.u64 t, %1; cvt.u32.u64 %0, t; }"
        : "=r"(a) : "l"(p));
    return a;
}
__device__ __forceinline__ float sqrt_fast(float x) {
    float y; asm("sqrt.approx.f32 %0, %1;" : "=f"(y) : "f"(x)); return y;
}
__device__ __forceinline__ float lg2_fast(float x) {
    float y; asm("lg2.approx.f32 %0, %1;" : "=f"(y) : "f"(x)); return y;
}
__device__ __forceinline__ float ex2_fast(float x) {
    float y; asm("ex2.approx.f32 %0, %1;" : "=f"(y) : "f"(x)); return y;
}
__device__ __forceinline__ void cpa16(uint32_t dst, const void* src) {
    asm volatile("cp.async.cg.shared.global [%0], [%1], 16;"
                 :: "r"(dst), "l"(src) : "memory");
}
__device__ __forceinline__ void ldsm4(uint32_t* r, uint32_t addr) {
    asm volatile("ldmatrix.sync.aligned.m8n8.x4.shared.b16 {%0,%1,%2,%3}, [%4];"
                 : "=r"(r[0]), "=r"(r[1]), "=r"(r[2]), "=r"(r[3]) : "r"(addr));
}
__device__ __forceinline__ void mma16816(float* d, const uint32_t* a, const uint32_t* b) {
    asm volatile(
        "mma.sync.aligned.m16n8k16.row.col.f32.f16.f16.f32 "
        "{%0,%1,%2,%3}, {%4,%5,%6,%7}, {%8,%9}, {%0,%1,%2,%3};"
        : "+f"(d[0]), "+f"(d[1]), "+f"(d[2]), "+f"(d[3])
        : "r"(a[0]), "r"(a[1]), "r"(a[2]), "r"(a[3]), "r"(b[0]), "r"(b[1]));
}

// ---------------------------------------------------------------------------
// Kernel 0: fully parallel fp16 conversion + norms + zero accumulators.
// (R12-identical: 224 threads/block, 1 row/block, measured 9.0us)
// ---------------------------------------------------------------------------
__global__ void __launch_bounds__(224) prep_k(const float* __restrict__ X,
                                              const float* __restrict__ E) {
    int row = blockIdx.x;
    int t = threadIdx.x;
    int lane = t & 31, w = t >> 5;
    float s = 0.f;        // X-norm contribution
    float se = 0.f;       // E-norm contribution

    if (t < 196) {
        float4 v = *(const float4*)(X + (size_t)row * DH + t * 4);
        __half2 h01 = __floats2half2_rn(v.x, v.y);
        __half2 h23 = __floats2half2_rn(v.z, v.w);
        float2 f0 = __half22float2(h01);
        float2 f1 = __half22float2(h23);
        s = fmaf(f0.x, f0.x, fmaf(f0.y, f0.y, fmaf(f1.x, f1.x, f1.y * f1.y)));
        uint2 pk = make_uint2(h2u(h01), h2u(h23));
        *(uint2*)(g_Xh + (size_t)row * DHP + t * 4) = pk;
    } else if (t < 208) {
        *(uint2*)(g_Xh + (size_t)row * DHP + DH + (t - 196) * 4) = make_uint2(0u, 0u);
    } else {
        int k = t - 208;
        __half h = __float2half(E[(size_t)row * 32 + k]);
        g_Eh[(size_t)row * DE + k] = h;
        float v = __half2float(h);
        se = v * v;
    }

    // per-warp reductions
    #pragma unroll
    for (int o = 16; o; o >>= 1) {
        s  += __shfl_xor_sync(0xffffffffu, s, o);
        se += __shfl_xor_sync(0xffffffffu, se, o);
    }
    __shared__ float ws[7], wse;
    if (lane == 0) {
        ws[w] = s;
        if (w == 6) wse = se;
    }
    __syncthreads();
    if (t == 0) {
        float tot = 0.f;
        #pragma unroll
        for (int q = 0; q < 7; q++) tot += ws[q];
        g_sqh[row] = tot;
        g_sql[row] = wse;
        g_Sh[row] = 0.0; g_Sl[row] = 0.0; g_Shh[row] = 0.0;
        g_Sll[row] = 0.0; g_Shl[row] = 0.0;
        if (row == 0) g_done = 0u;
    }
}

// ---------------------------------------------------------------------------
// Kernel 1: HMMA pairwise-moment tiles — R12 body + peeled last chunk
// ---------------------------------------------------------------------------
__global__ void __launch_bounds__(256, 2) pair_k() {
    extern __shared__ __align__(16) char smem[];
    const uint32_t sb = s2u(smem);
    const int tid = threadIdx.x;
    const int lane = tid & 31, wid = tid >> 5;
    const int wr = wid >> 2, wc = wid & 3;

    // triangular tile decode
    int idx = blockIdx.x, bi = 0;
    while ((bi + 1) * (65 - (bi + 1)) / 2 <= idx) bi++;
    int bj = bi + (idx - bi * (65 - bi) / 2);
    const bool offdiag = (bi != bj);
    const int i0 = bi * 128, j0 = bj * 128;

    float* nhI = (float*)(smem + SM_NHI);
    float* nhJ = (float*)(smem + SM_NHJ);
    float* nlI = (float*)(smem + SM_NLI);
    float* nlJ = (float*)(smem + SM_NLJ);
    if (tid < 128) {
        nhI[tid] = g_sqh[i0 + tid];
        nlI[tid] = g_sql[i0 + tid];
    } else {
        int r = tid - 128;
        nhJ[r] = g_sqh[j0 + r];
        nlJ[r] = g_sql[j0 + r];
    }

    const __half* XA = g_Xh + (size_t)i0 * DHP;
    const __half* XB = g_Xh + (size_t)j0 * DHP;

    // E tiles (1 cp.async per thread per side)
    {
        int row = tid >> 1, u = tid & 1;
        cpa16(sb + SM_EA + row * 32 + u * 16, g_Eh + (size_t)(i0 + row) * DE + u * 8);
        cpa16(sb + SM_EB + row * 32 + u * 16, g_Eh + (size_t)(j0 + row) * DE + u * 8);
    }
    // chunk 0
    #pragma unroll
    for (int p = 0; p < 4; p++) {
        int id = tid + p * 256;
        int row = id >> 3, u = id & 7;
        uint32_t sw = (uint32_t)((u ^ (row & 7)) << 4);
        cpa16(sb + SM_A + row * 128 + sw, XA + (size_t)row * DHP + u * 8);
        cpa16(sb + SM_B + row * 128 + sw, XB + (size_t)row * DHP + u * 8);
    }
    asm volatile("cp.async.commit_group;" ::: "memory");
    asm volatile("cp.async.wait_group 0;" ::: "memory");
    __syncthreads();

    // per-thread fragment address components
    const int rbaseA = wr * 64 + (lane & 15);
    const int duA    = lane >> 4;
    const int rmA    = rbaseA & 7;
    const int nbase  = wc * 32 + (lane & 7) + ((lane >> 4) << 3);
    const int duB    = (lane >> 3) & 1;
    const int rmB    = lane & 7;

    float acc[4][4][4];
    #pragma unroll
    for (int a = 0; a < 4; a++)
        #pragma unroll
        for (int b = 0; b < 4; b++)
            #pragma unroll
            for (int c = 0; c < 4; c++) acc[a][b][c] = 0.f;

    // ---------------- low-D (16) gram: single k-step ----------------
    {
        uint32_t ea[4][4], eb[2][4];
        #pragma unroll
        for (int mi = 0; mi < 4; mi++) {
            int rE = rbaseA + mi * 16;
            ldsm4(ea[mi], sb + SM_EA + rE * 32 + (duA << 4));
        }
        #pragma unroll
        for (int nt = 0; nt < 2; nt++) {
            int nE = nbase + nt * 16;
            ldsm4(eb[nt], sb + SM_EB + nE * 32 + (duB << 4));
        }
        #pragma unroll
        for (int mi = 0; mi < 4; mi++)
            #pragma unroll
            for (int ni = 0; ni < 4; ni++)
                mma16816(acc[mi][ni], ea[mi], &eb[ni >> 1][(ni & 1) * 2]);
    }
    // convert to l distances (half2), reset acc
    __half2 lhp[4][4][2];
    #pragma unroll
    for (int mi = 0; mi < 4; mi++) {
        int r0 = wr * 64 + mi * 16 + (lane >> 2), r1 = r0 + 8;
        float nl0 = nlI[r0], nl1 = nlI[r1];
        #pragma unroll
        for (int ni = 0; ni < 4; ni++) {
            int c0 = wc * 32 + ni * 8 + ((lane & 3) << 1), c1 = c0 + 1;
            float ol0 = nlJ[c0], ol1 = nlJ[c1];
            float l00 = sqrt_fast(fmaxf(fmaf(-2.f, acc[mi][ni][0], nl0 + ol0), 0.f));
            float l01 = sqrt_fast(fmaxf(fmaf(-2.f, acc[mi][ni][1], nl0 + ol1), 0.f));
            float l10 = sqrt_fast(fmaxf(fmaf(-2.f, acc[mi][ni][2], nl1 + ol0), 0.f));
            float l11 = sqrt_fast(fmaxf(fmaf(-2.f, acc[mi][ni][3], nl1 + ol1), 0.f));
            lhp[mi][ni][0] = __floats2half2_rn(l00, l01);
            lhp[mi][ni][1] = __floats2half2_rn(l10, l11);
            acc[mi][ni][0] = 0.f; acc[mi][ni][1] = 0.f;
            acc[mi][ni][2] = 0.f; acc[mi][ni][3] = 0.f;
        }
    }

    // ---------------- high-D mainloop: chunks 0..11 (full 4 ks each) -------
    for (int c = 0; c < NCH - 1; c++) {
        {
            uint32_t dA = sb + SM_A + (((c + 1) & 1) << 14);
            uint32_t dB = sb + SM_B + (((c + 1) & 1) << 14);
            const __half* pA = XA + (c + 1) * 64;
            const __half* pB = XB + (c + 1) * 64;
            #pragma unroll
            for (int p = 0; p < 4; p++) {
                int id = tid + p * 256;
                int row = id >> 3, u = id & 7;
                uint32_t sw = (uint32_t)((u ^ (row & 7)) << 4);
                cpa16(dA + row * 128 + sw, pA + (size_t)row * DHP + u * 8);
                cpa16(dB + row * 128 + sw, pB + (size_t)row * DHP + u * 8);
            }
            asm volatile("cp.async.commit_group;" ::: "memory");
            asm volatile("cp.async.wait_group 1;" ::: "memory");
        }
        __syncthreads();

        uint32_t bA = sb + SM_A + ((c & 1) << 14);
        uint32_t bB = sb + SM_B + ((c & 1) << 14);
        #pragma unroll
        for (int ks = 0; ks < 4; ks++) {
            uint32_t afr[4][4], bfr[2][4];
            #pragma unroll
            for (int mi = 0; mi < 4; mi++) {
                int row = rbaseA + mi * 16;
                ldsm4(afr[mi], bA + row * 128 + (((2 * ks + duA) ^ rmA) << 4));
            }
            #pragma unroll
            for (int nt = 0; nt < 2; nt++) {
                int nb = nbase + nt * 16;
                ldsm4(bfr[nt], bB + nb * 128 + (((2 * ks + duB) ^ rmB) << 4));
            }
            #pragma unroll
            for (int mi = 0; mi < 4; mi++)
                #pragma unroll
                for (int ni = 0; ni < 4; ni++)
                    mma16816(acc[mi][ni], afr[mi], &bfr[ni >> 1][(ni & 1) * 2]);
        }
        __syncthreads();
    }
    // ---------------- peeled chunk 12: cols 768..831, only ks=0 is real ----
    {
        asm volatile("cp.async.wait_group 0;" ::: "memory");
        __syncthreads();
        uint32_t bA = sb + SM_A;        // chunk 12 landed in buffer 0 (12&1==0)
        uint32_t bB = sb + SM_B;
        uint32_t afr[4][4], bfr[2][4];
        #pragma unroll
        for (int mi = 0; mi < 4; mi++) {
            int row = rbaseA + mi * 16;
            ldsm4(afr[mi], bA + row * 128 + ((duA ^ rmA) << 4));
        }
        #pragma unroll
        for (int nt = 0; nt < 2; nt++) {
            int nb = nbase + nt * 16;
            ldsm4(bfr[nt], bB + nb * 128 + ((duB ^ rmB) << 4));
        }
        #pragma unroll
        for (int mi = 0; mi < 4; mi++)
            #pragma unroll
            for (int ni = 0; ni < 4; ni++)
                mma16816(acc[mi][ni], afr[mi], &bfr[ni >> 1][(ni & 1) * 2]);
        __syncthreads();
    }

    // ---------------- epilogue: distances + moments ----------------
    float* rowSm = (float*)(smem + SM_ROW);
    float* colSm = (float*)(smem + SM_COL);
    float cacc[4][2][5];
    #pragma unroll
    for (int ni = 0; ni < 4; ni++)
        #pragma unroll
        for (int q = 0; q < 2; q++)
            #pragma unroll
            for (int m = 0; m < 5; m++) cacc[ni][q][m] = 0.f;

    #pragma unroll
    for (int mi = 0; mi < 4; mi++) {
        int r0 = wr * 64 + mi * 16 + (lane >> 2), r1 = r0 + 8;
        float nh0 = nhI[r0], nh1 = nhI[r1];
        float rA[5] = {0.f, 0.f, 0.f, 0.f, 0.f};
        float rB[5] = {0.f, 0.f, 0.f, 0.f, 0.f};
        #pragma unroll
        for (int ni = 0; ni < 4; ni++) {
            int c0 = wc * 32 + ni * 8 + ((lane & 3) << 1), c1 = c0 + 1;
            float oh0 = nhJ[c0], oh1 = nhJ[c1];
            float h00 = sqrt_fast(fmaxf(fmaf(-2.f, acc[mi][ni][0], nh0 + oh0), 0.f));
            float h01 = sqrt_fast(fmaxf(fmaf(-2.f, acc[mi][ni][1], nh0 + oh1), 0.f));
            float h10 = sqrt_fast(fmaxf(fmaf(-2.f, acc[mi][ni][2], nh1 + oh0), 0.f));
            float h11 = sqrt_fast(fmaxf(fmaf(-2.f, acc[mi][ni][3], nh1 + oh1), 0.f));
            float2 lp0 = __half22float2(lhp[mi][ni][0]);
            float2 lp1 = __half22float2(lhp[mi][ni][1]);
            rA[0] += h00 + h01;
            rA[1] += lp0.x + lp0.y;
            rA[2] = fmaf(h00, h00, fmaf(h01, h01, rA[2]));
            rA[3] = fmaf(lp0.x, lp0.x, fmaf(lp0.y, lp0.y, rA[3]));
            rA[4] = fmaf(h00, lp0.x, fmaf(h01, lp0.y, rA[4]));
            rB[0] += h10 + h11;
            rB[1] += lp1.x + lp1.y;
            rB[2] = fmaf(h10, h10, fmaf(h11, h11, rB[2]));
            rB[3] = fmaf(lp1.x, lp1.x, fmaf(lp1.y, lp1.y, rB[3]));
            rB[4] = fmaf(h10, lp1.x, fmaf(h11, lp1.y, rB[4]));
            cacc[ni][0][0] += h00 + h10;
            cacc[ni][0][1] += lp0.x + lp1.x;
            cacc[ni][0][2] = fmaf(h00, h00, fmaf(h10, h10, cacc[ni][0][2]));
            cacc[ni][0][3] = fmaf(lp0.x, lp0.x, fmaf(lp1.x, lp1.x, cacc[ni][0][3]));
            cacc[ni][0][4] = fmaf(h00, lp0.x, fmaf(h10, lp1.x, cacc[ni][0][4]));
            cacc[ni][1][0] += h01 + h11;
            cacc[ni][1][1] += lp0.y + lp1.y;
            cacc[ni][1][2] = fmaf(h01, h01, fmaf(h11, h11, cacc[ni][1][2]));
            cacc[ni][1][3] = fmaf(lp0.y, lp0.y, fmaf(lp1.y, lp1.y, cacc[ni][1][3]));
            cacc[ni][1][4] = fmaf(h01, lp0.y, fmaf(h11, lp1.y, cacc[ni][1][4]));
        }
        #pragma unroll
        for (int m = 0; m < 5; m++) {
            rA[m] += __shfl_xor_sync(0xffffffffu, rA[m], 1);
            rA[m] += __shfl_xor_sync(0xffffffffu, rA[m], 2);
            rB[m] += __shfl_xor_sync(0xffffffffu, rB[m], 1);
            rB[m] += __shfl_xor_sync(0xffffffffu, rB[m], 2);
        }
        if ((lane & 3) == 0) {
            #pragma unroll
            for (int m = 0; m < 5; m++) {
                rowSm[(wc * 128 + r0) * 5 + m] = rA[m];
                rowSm[(wc * 128 + r1) * 5 + m] = rB[m];
            }
        }
    }
    #pragma unroll
    for (int ni = 0; ni < 4; ni++)
        #pragma unroll
        for (int q = 0; q < 2; q++)
            #pragma unroll
            for (int m = 0; m < 5; m++) {
                float v = cacc[ni][q][m];
                v += __shfl_xor_sync(0xffffffffu, v, 4);
                v += __shfl_xor_sync(0xffffffffu, v, 8);
                v += __shfl_xor_sync(0xffffffffu, v, 16);
                cacc[ni][q][m] = v;
            }
    if (lane < 4) {
        #pragma unroll
        for (int ni = 0; ni < 4; ni++) {
            int c0 = wc * 32 + ni * 8 + (lane << 1);
            #pragma unroll
            for (int m = 0; m < 5; m++) {
                colSm[(wr * 128 + c0) * 5 + m]     = cacc[ni][0][m];
                colSm[(wr * 128 + c0 + 1) * 5 + m] = cacc[ni][1][m];
            }
        }
    }
    __syncthreads();

    if (tid < 128) {
        int r = tid;
        float s0 = 0.f, s1 = 0.f, s2 = 0.f, s3 = 0.f, s4 = 0.f;
        #pragma unroll
        for (int w = 0; w < 4; w++) {
            const float* p = &rowSm[(w * 128 + r) * 5];
            s0 += p[0]; s1 += p[1]; s2 += p[2]; s3 += p[3]; s4 += p[4];
        }
        int gi = i0 + r;
        atomicAdd(&g_Sh[gi],  (double)s0);
        atomicAdd(&g_Sl[gi],  (double)s1);
        atomicAdd(&g_Shh[gi], (double)s2);
        atomicAdd(&g_Sll[gi], (double)s3);
        atomicAdd(&g_Shl[gi], (double)s4);
    } else if (offdiag) {
        int cjj = tid - 128;
        float s0 = 0.f, s1 = 0.f, s2 = 0.f, s3 = 0.f, s4 = 0.f;
        #pragma unroll
        for (int w = 0; w < 2; w++) {
            const float* p = &colSm[(w * 128 + cjj) * 5];
            s0 += p[0]; s1 += p[1]; s2 += p[2]; s3 += p[3]; s4 += p[4];
        }
        int gj = j0 + cjj;
        atomicAdd(&g_Sh[gj],  (double)s0);
        atomicAdd(&g_Sl[gj],  (double)s1);
        atomicAdd(&g_Shh[gj], (double)s2);
        atomicAdd(&g_Sll[gj], (double)s3);
        atomicAdd(&g_Shl[gj], (double)s4);
    }
}

// ---------------------------------------------------------------------------
// Kernel 2: parallel tail — CE partials (blocks 0..95) + corr partials
// (blocks 96..111); LAST block reduces all partials and writes out.
// (R12-identical)
// ---------------------------------------------------------------------------
__global__ void __launch_bounds__(256) work_k(const float* __restrict__ E,
                                              const int* __restrict__ perm,
                                              float* __restrict__ out) {
    int b = blockIdx.x;
    int t = threadIdx.x;
    float val = 0.f;
    if (b < NCEB) {
        int idx = b * 256 + t;   // exactly NTOT items across 96 blocks
        float sq = 0.f;
        if (idx < Bn) {
            const float* p = E + (size_t)idx * 32;
            #pragma unroll
            for (int k = 0; k < DE; k++) { float d = p[k] - p[DE + k]; sq = fmaf(d, d, sq); }
            float pw = (sq > 0.f) ? ex2_fast(0.5f * PW * lg2_fast(sq)) : 0.f;
            float pd = 1.f / (1.f + A_C * pw);
            val = -0.69314718056f * lg2_fast(fmaxf(pd, EPSc));
        } else {
            int j = idx - Bn;
            const float* pt = E + (size_t)(j / NSR) * 32;
            const float* pf = E + (size_t)(perm[j] / NSR) * 32 + DE;
            #pragma unroll
            for (int k = 0; k < DE; k++) { float d = pt[k] - pf[k]; sq = fmaf(d, d, sq); }
            float pw = (sq > 0.f) ? ex2_fast(0.5f * PW * lg2_fast(sq)) : 0.f;
            float pd = 1.f / (1.f + A_C * pw);
            val = -0.69314718056f * lg2_fast(fmaxf(1.f - pd, EPSc));
        }
    } else {
        int i = (b - NCEB) * 256 + t;
        const double invB = 1.0 / (double)Bn;
        double Sh = g_Sh[i], Sl = g_Sl[i];
        float num = (float)(g_Shl[i] - Sh * Sl * invB);
        float vh  = (float)fmax(g_Shh[i] - Sh * Sh * invB, 0.0);
        float vl  = (float)fmax(g_Sll[i] - Sl * Sl * invB, 0.0);
        val = num * rsqrtf(fmaxf(vh, 1e-30f)) * rsqrtf(fmaxf(vl, 1e-30f));
    }
    #pragma unroll
    for (int o = 16; o; o >>= 1) val += __shfl_xor_sync(0xffffffffu, val, o);
    __shared__ float ws[8];
    __shared__ unsigned sticket;
    if ((t & 31) == 0) ws[t >> 5] = val;
    __syncthreads();
    if (t == 0) {
        float s2 = 0.f;
        #pragma unroll
        for (int w = 0; w < 8; w++) s2 += ws[w];
        g_part[b] = (double)s2;
        __threadfence();
        sticket = atomicAdd(&g_done, 1u);
    }
    __syncthreads();
    if (sticket == NWRK - 1) {
        // last block: reduce all partials
        double v = (t < NWRK) ? ((volatile double*)g_part)[t] : 0.0;
        bool isCE = (t < NCEB);
        double ce = isCE ? v : 0.0;
        double co = (!isCE && t < NWRK) ? v : 0.0;
        #pragma unroll
        for (int o = 16; o; o >>= 1) {
            ce += __shfl_xor_sync(0xffffffffu, ce, o);
            co += __shfl_xor_sync(0xffffffffu, co, o);
        }
        __shared__ double rce[8], rco[8];
        if ((t & 31) == 0) { rce[t >> 5] = ce; rco[t >> 5] = co; }
        __syncthreads();
        if (t == 0) {
            double sce = 0.0, sco = 0.0;
            #pragma unroll
            for (int w = 0; w < 8; w++) { sce += rce[w]; sco += rco[w]; }
            out[0] = (float)(ALPHA * (sce / (double)NTOT) - BETA * (sco / (double)Bn));
        }
    }
}

// ---------------------------------------------------------------------------
extern "C" void kernel_launch(void* const* d_in, const int* in_sizes, int n_in,
                              void* d_out, int out_size) {
    (void)in_sizes; (void)n_in; (void)out_size;
    const float* E    = (const float*)d_in[0];
    const float* X    = (const float*)d_in[1];
    const int*   perm = (const int*)d_in[2];
    float* out = (float*)d_out;

    cudaFuncSetAttribute(pair_k, cudaFuncAttributeMaxDynamicSharedMemorySize, SM_TOT);

    prep_k<<<Bn, 224>>>(X, E);
    pair_k<<<NBLK, 256, SM_TOT>>>();
    work_k<<<NWRK, 256>>>(E, perm, out);
}